// round 1
// baseline (speedup 1.0000x reference)
#include <cuda_runtime.h>

#define NN 8192

// Scratch (allocation-free rule: __device__ globals)
__device__ float g_conv[NN];
__device__ float g_h[NN];

// Kernel 1: per-node 16-wide dot + bias + sigmoid
__global__ void conv_sigmoid_kernel(const float* __restrict__ nf,
                                    const float* __restrict__ cw,
                                    const float* __restrict__ cb) {
    int i = blockIdx.x * blockDim.x + threadIdx.x;
    if (i >= NN) return;
    const float4* row = reinterpret_cast<const float4*>(nf + (size_t)i * 16);
    float4 w0 = reinterpret_cast<const float4*>(cw)[0];
    float4 w1 = reinterpret_cast<const float4*>(cw)[1];
    float4 w2 = reinterpret_cast<const float4*>(cw)[2];
    float4 w3 = reinterpret_cast<const float4*>(cw)[3];
    float4 a0 = row[0], a1 = row[1], a2 = row[2], a3 = row[3];
    float s = a0.x*w0.x + a0.y*w0.y + a0.z*w0.z + a0.w*w0.w
            + a1.x*w1.x + a1.y*w1.y + a1.z*w1.z + a1.w*w1.w
            + a2.x*w2.x + a2.y*w2.y + a2.z*w2.z + a2.w*w2.w
            + a3.x*w3.x + a3.y*w3.y + a3.z*w3.z + a3.w*w3.w;
    s += cb[0];
    g_conv[i] = 1.0f / (1.0f + __expf(-s));
}

// Kernel 2/3: y[row] = act(W[row,:] . x + b[row]); one row per block.
// APPLY_TANH=1 -> tanh activation, 0 -> identity.
template <int APPLY_TANH>
__global__ void __launch_bounds__(256) matvec_kernel(
    const float* __restrict__ W,
    const float* __restrict__ b,
    const float* __restrict__ x,
    float* __restrict__ y) {
    const int row = blockIdx.x;
    const float4* __restrict__ W4 = reinterpret_cast<const float4*>(W + (size_t)row * NN);
    const float4* __restrict__ x4 = reinterpret_cast<const float4*>(x);

    float s = 0.0f;
    // NN/4 = 2048 float4 per row, 256 threads -> 8 iterations, fully unrolled
    #pragma unroll
    for (int it = 0; it < (NN / 4) / 256; ++it) {
        int i = it * 256 + threadIdx.x;
        float4 a = W4[i];
        float4 v = x4[i];
        s += a.x * v.x + a.y * v.y + a.z * v.z + a.w * v.w;
    }

    // Block reduction: warp shuffle, then cross-warp via shared
    #pragma unroll
    for (int o = 16; o > 0; o >>= 1) s += __shfl_xor_sync(0xffffffffu, s, o);

    __shared__ float red[8];
    if ((threadIdx.x & 31) == 0) red[threadIdx.x >> 5] = s;
    __syncthreads();
    if (threadIdx.x < 8) {
        s = red[threadIdx.x];
        #pragma unroll
        for (int o = 4; o > 0; o >>= 1) s += __shfl_xor_sync(0x000000ffu, s, o);
        if (threadIdx.x == 0) {
            s += b[row];
            y[row] = APPLY_TANH ? tanhf(s) : s;
        }
    }
}

extern "C" void kernel_launch(void* const* d_in, const int* in_sizes, int n_in,
                              void* d_out, int out_size) {
    const float* node_features = (const float*)d_in[0]; // (8192, 16)
    const float* conv_w        = (const float*)d_in[1]; // (16,)
    const float* conv_b        = (const float*)d_in[2]; // scalar
    const float* W1            = (const float*)d_in[3]; // (8192, 8192)
    const float* b1            = (const float*)d_in[4]; // (8192,)
    const float* W2            = (const float*)d_in[5]; // (8192, 8192)
    const float* b2            = (const float*)d_in[6]; // (8192,)
    float* out = (float*)d_out;

    float* conv_feats;
    float* h;
    cudaGetSymbolAddress((void**)&conv_feats, g_conv);
    cudaGetSymbolAddress((void**)&h, g_h);

    conv_sigmoid_kernel<<<NN / 256, 256>>>(node_features, conv_w, conv_b);
    matvec_kernel<1><<<NN, 256>>>(W1, b1, conv_feats, h);
    matvec_kernel<0><<<NN, 256>>>(W2, b2, h, out);
}